// round 1
// baseline (speedup 1.0000x reference)
#include <cuda_runtime.h>
#include <cstdint>

// YOLO loss: fused per-cell loss + two-stage deterministic reduction.
// Inputs: d_in[0] = y (pred), d_in[1] = gt (target), each (16384,7,7,30) fp32.
// Output: scalar fp32.

#define NCELLS (16384 * 7 * 7)          // 802816
#define THREADS 256
#define NBLOCKS ((NCELLS + THREADS - 1) / THREADS)  // 3136

__device__ float g_partial[4096];

__device__ __forceinline__ float iou_f(float x1, float y1, float w1, float h1,
                                       float x2, float y2, float w2, float h2) {
    float xl = fmaxf(x1 - w1 * 0.5f, x2 - w2 * 0.5f);
    float yt = fmaxf(y1 - h1 * 0.5f, y2 - h2 * 0.5f);
    float xr = fminf(x1 + w1 * 0.5f, x2 + w2 * 0.5f);
    float yb = fminf(y1 + h1 * 0.5f, y2 + h2 * 0.5f);
    bool valid = (xr >= xl) && (yb >= yt);
    float inter = (xr - xl) * (yb - yt);
    float uni = w1 * h1 + w2 * h2 - inter;
    float safe = (uni == 0.0f) ? 1.0f : uni;
    return valid ? (inter / safe) : 0.0f;
}

__global__ void __launch_bounds__(THREADS)
yolo_partial_kernel(const float* __restrict__ pred,
                    const float* __restrict__ tgt,
                    float* __restrict__ partial) {
    int cell = blockIdx.x * blockDim.x + threadIdx.x;
    float loss = 0.0f;

    if (cell < NCELLS) {
        // 30 floats per cell; 120-byte stride is 8-aligned -> float2 loads.
        const float2* p2 = reinterpret_cast<const float2*>(pred) + (size_t)cell * 15;
        const float2* t2 = reinterpret_cast<const float2*>(tgt)  + (size_t)cell * 15;

        float p[30], t[30];
#pragma unroll
        for (int i = 0; i < 15; i++) {
            float2 v = __ldg(&p2[i]);
            p[2 * i] = v.x; p[2 * i + 1] = v.y;
        }
#pragma unroll
        for (int i = 0; i < 15; i++) {
            float2 v = __ldg(&t2[i]);
            t[2 * i] = v.x; t[2 * i + 1] = v.y;
        }

        float t4 = t[4];
        float obj   = (t4 > 0.0f)  ? 1.0f : 0.0f;
        float noobj = (t4 == 0.0f) ? 1.0f : 0.0f;

        // class loss (channels 10..29)
        float cls = 0.0f;
#pragma unroll
        for (int c = 10; c < 30; c++) {
            float d = t[c] - p[c];
            cls += d * d;
        }
        cls *= obj;

        // no-object confidence loss
        float dno = t4 - p[4];
        float conf_noobj = noobj * dno * dno;

        // IoUs of both predicted boxes vs target box
        float iou1 = iou_f(t[0], t[1], t[2], t[3], p[0], p[1], p[2], p[3]);
        float iou2 = iou_f(t[0], t[1], t[2], t[3], p[5], p[6], p[7], p[8]);
        float resp1 = (iou1 > iou2) ? 1.0f : 0.0f;
        float m1 = obj * resp1;
        float m2 = obj * (1.0f - resp1);

        float d1 = iou1 - p[4];
        float d2 = iou2 - p[9];
        float conf_obj = m1 * d1 * d1 + m2 * d2 * d2;

        float dx1 = t[0] - p[0], dy1 = t[1] - p[1];
        float dx2 = t[0] - p[5], dy2 = t[1] - p[6];
        float xy = m1 * (dx1 * dx1 + dy1 * dy1) + m2 * (dx2 * dx2 + dy2 * dy2);

        float dw1 = t[2] - p[2], dh1 = t[3] - p[3];
        float dw2 = t[2] - p[7], dh2 = t[3] - p[8];
        float wh = m1 * (dw1 * dw1 + dh1 * dh1) + m2 * (dw2 * dw2 + dh2 * dh2);

        loss = 5.0f * (xy + wh) + conf_obj + 0.5f * conf_noobj + cls;
    }

    // warp reduce
#pragma unroll
    for (int off = 16; off > 0; off >>= 1)
        loss += __shfl_down_sync(0xFFFFFFFFu, loss, off);

    __shared__ float s[THREADS / 32];
    int lane = threadIdx.x & 31;
    int wid = threadIdx.x >> 5;
    if (lane == 0) s[wid] = loss;
    __syncthreads();

    if (wid == 0) {
        float v = (lane < THREADS / 32) ? s[lane] : 0.0f;
#pragma unroll
        for (int off = 4; off > 0; off >>= 1)
            v += __shfl_down_sync(0xFFFFFFFFu, v, off);
        if (lane == 0) partial[blockIdx.x] = v;
    }
}

__global__ void __launch_bounds__(256)
yolo_final_kernel(const float* __restrict__ partial, float* __restrict__ out, int n) {
    __shared__ double s[256];
    double acc = 0.0;
    for (int i = threadIdx.x; i < n; i += 256)
        acc += (double)partial[i];
    s[threadIdx.x] = acc;
    __syncthreads();
    for (int stride = 128; stride > 0; stride >>= 1) {
        if (threadIdx.x < stride) s[threadIdx.x] += s[threadIdx.x + stride];
        __syncthreads();
    }
    if (threadIdx.x == 0)
        out[0] = (float)(s[0] / 16384.0);
}

extern "C" void kernel_launch(void* const* d_in, const int* in_sizes, int n_in,
                              void* d_out, int out_size) {
    const float* y  = (const float*)d_in[0];
    const float* gt = (const float*)d_in[1];
    float* out = (float*)d_out;

    float* partial;
    cudaGetSymbolAddress((void**)&partial, g_partial);

    yolo_partial_kernel<<<NBLOCKS, THREADS>>>(y, gt, partial);
    yolo_final_kernel<<<1, 256>>>(partial, out, NBLOCKS);
}